// round 8
// baseline (speedup 1.0000x reference)
#include <cuda_runtime.h>
#include <math.h>
#include <stdint.h>

typedef unsigned long long ull;

#define T_STEPS 1024
#define BATCH   64
#define IN_DIM  512
#define H_DIM   1024

#define NCTA         128
#define SCAN_THREADS 512
#define NWARPS       16
#define ROWS_CTA     32          // 2 batch-groups of 32 rows
#define COLS_CTA     16          // 64 col-groups of 16 cols
#define KPW          (H_DIM / NWARPS)   // 64 k per warp

// Transposed hidden state, double-buffered: g_ht[p][col*BATCH + row]
__device__ float g_ht[2][H_DIM * BATCH];
// Grid barrier: monotonic arrival counter + separately-polled epoch word
__device__ ull g_count = 0ULL;
__device__ ull g_epoch = 0ULL;

// ---------------------------------------------------------------------------
// packed f32x2 helpers (Blackwell sm_103a)
// ---------------------------------------------------------------------------
__device__ __forceinline__ ull pack2(float a, float b)
{
    ull r; asm("mov.b64 %0, {%1, %2};" : "=l"(r) : "f"(a), "f"(b)); return r;
}
__device__ __forceinline__ void unpack2(ull v, float& a, float& b)
{
    asm("mov.b64 {%0, %1}, %2;" : "=f"(a), "=f"(b) : "l"(v));
}
__device__ __forceinline__ void fma2(ull& acc, ull a, ull b)
{
    asm("fma.rn.f32x2 %0, %1, %2, %0;" : "+l"(acc) : "l"(a), "l"(b));
}
__device__ __forceinline__ ull add2(ull a, ull b)
{
    ull r; asm("add.rn.f32x2 %0, %1, %2;" : "=l"(r) : "l"(a), "l"(b)); return r;
}
__device__ __forceinline__ ull mk64(unsigned lo, unsigned hi)
{
    ull r; asm("mov.b64 %0, {%1, %2};" : "=l"(r) : "r"(lo), "r"(hi)); return r;
}

// ---------------------------------------------------------------------------
// Kernel 1: xproj = x @ Wx + b  (out doubles as xproj buffer) — R6 version
// M=65536, K=512, N=1024. BM=64, BN=64, BK=16; 256 threads; 4x4 microtile.
// ---------------------------------------------------------------------------
__global__ void __launch_bounds__(256) xproj_kernel(
    const float* __restrict__ x,
    const float* __restrict__ W,     // full (IN+H, H); Wx = rows [0,512)
    const float* __restrict__ bias,
    float* __restrict__ out)
{
    __shared__ float As[16][64];     // [k][m]
    __shared__ float Bs[16][64];     // [k][n]

    const int tid  = threadIdx.x;
    const int row0 = blockIdx.y * 64;
    const int col0 = blockIdx.x * 64;

    const int ty = tid >> 4;               // 0..15
    const int tx = tid & 15;               // 0..15

    const int lmA = tid >> 2;              // 0..63
    const int lkA = (tid & 3) << 2;        // 0,4,8,12
    const int lkB = tid >> 4;              // 0..15
    const int lnB = (tid & 15) << 2;       // 0..60

    ull acc01[4], acc23[4];
#pragma unroll
    for (int i = 0; i < 4; ++i) { acc01[i] = 0ULL; acc23[i] = 0ULL; }

    const float* xg = x + (size_t)(row0 + lmA) * IN_DIM + lkA;

    for (int k0 = 0; k0 < IN_DIM; k0 += 16) {
        float4 av = *(const float4*)(xg + k0);
        As[lkA + 0][lmA] = av.x;
        As[lkA + 1][lmA] = av.y;
        As[lkA + 2][lmA] = av.z;
        As[lkA + 3][lmA] = av.w;

        float4 bv = *(const float4*)(W + (size_t)(k0 + lkB) * H_DIM + col0 + lnB);
        *(float4*)&Bs[lkB][lnB] = bv;

        __syncthreads();
#pragma unroll
        for (int k = 0; k < 16; ++k) {
            float4 a = *(const float4*)&As[k][ty << 2];
            ulonglong2 b = *(const ulonglong2*)&Bs[k][tx << 2];
            ull ax = pack2(a.x, a.x);
            ull ay = pack2(a.y, a.y);
            ull az = pack2(a.z, a.z);
            ull aw = pack2(a.w, a.w);
            fma2(acc01[0], ax, b.x); fma2(acc23[0], ax, b.y);
            fma2(acc01[1], ay, b.x); fma2(acc23[1], ay, b.y);
            fma2(acc01[2], az, b.x); fma2(acc23[2], az, b.y);
            fma2(acc01[3], aw, b.x); fma2(acc23[3], aw, b.y);
        }
        __syncthreads();
    }

    float4 bb = *(const float4*)(bias + col0 + (tx << 2));
#pragma unroll
    for (int i = 0; i < 4; ++i) {
        float s0, s1, s2, s3;
        unpack2(acc01[i], s0, s1);
        unpack2(acc23[i], s2, s3);
        float4 o;
        o.x = s0 + bb.x;
        o.y = s1 + bb.y;
        o.z = s2 + bb.z;
        o.w = s3 + bb.w;
        *(float4*)(out + (size_t)(row0 + (ty << 2) + i) * H_DIM + col0 + (tx << 2)) = o;
    }
}

// ---------------------------------------------------------------------------
// Counter+epoch grid barrier (release publish / acquire poll)
// ---------------------------------------------------------------------------
__device__ __forceinline__ void grid_barrier()
{
    __syncthreads();
    if (threadIdx.x == 0) {
        __threadfence();
        ull old = atomicAdd(&g_count, 1ULL);
        ull target = (old / NCTA + 1ULL) * (ull)NCTA;
        if (old + 1ULL == target) {
            asm volatile("st.release.gpu.global.u64 [%0], %1;" :: "l"(&g_epoch), "l"(target));
        } else {
            ull cur;
            do {
                asm volatile("ld.acquire.gpu.global.u64 %0, [%1];" : "=l"(cur) : "l"(&g_epoch));
            } while (cur < target);
        }
    }
    __syncthreads();
}

// ---------------------------------------------------------------------------
// Kernel 2: persistent recurrent scan — direct-LDG (L2-resident h) version.
// 128 CTAs (2 batch-groups x 64 col-groups) x 512 threads (16 warps).
// CTA tile: 32 rows x 16 cols. Warp layout: lane = rg(0..7) + 8*cg(0..3);
// thread: rows rg*4..+3, cols cg*4..+3 (8 f32x2 row-pair accumulators).
// Warp w covers k in [w*64, w*64+64): loads h rows straight from L2 via
// __ldcg (one 128B line per LDG.128, shared by 64 CTAs -> 16MB/step L2),
// weights dup-packed (w,w) resident in smem [k][16] (128KB, conflict-free).
// No staging, no per-chunk syncs: one __syncthreads (reduction) + barrier.
// ---------------------------------------------------------------------------
__global__ void __launch_bounds__(SCAN_THREADS) scan_kernel(
    const float* __restrict__ hinit,  // initial h (B,H)
    const float* __restrict__ W,      // Wh = rows [512, 1536)
    float* __restrict__ out)
{
    extern __shared__ float smem[];
    ull*        wdup  = (ull*)smem;                       // [1024][16] ull = 128KB
    ulonglong2* red   = (ulonglong2*)(smem + 32768);      // [4][16][32] ull2 = 32KB
    ull*        red_u = (ull*)red;

    const int tid  = threadIdx.x;
    const int wid  = tid >> 5;                // warp 0..15
    const int lane = tid & 31;
    const int rg   = lane & 7;                // rows rg*4..rg*4+3
    const int cg   = lane >> 3;               // cols cg*4..cg*4+3
    const int bg   = blockIdx.x >> 6;         // batch group 0..1
    const int cgc  = blockIdx.x & 63;         // col group 0..63
    const int row0 = bg * ROWS_CTA;
    const int col0 = cgc * COLS_CTA;
    const int j0   = cg << 2;

    // Prologue A: transpose my tile of initial h into g_ht[0]
    {
        int cc = tid >> 5;        // 0..15
        int r  = tid & 31;        // 0..31
        g_ht[0][(col0 + cc) * BATCH + row0 + r] =
            hinit[(size_t)(row0 + r) * H_DIM + col0 + cc];
    }

    // Prologue B: dup-pack resident Wh slice, k-major: wdup[k][c] = (w,w)
    for (int i = tid; i < H_DIM * COLS_CTA; i += SCAN_THREADS) {
        int k = i >> 4;           // 0..1023
        int c = i & 15;           // 0..15
        float w = W[(size_t)(IN_DIM + k) * H_DIM + col0 + c];
        wdup[k * COLS_CTA + c] = pack2(w, w);
    }

    grid_barrier();   // transposes visible before step-0 loads

    const int kbase = wid * KPW;

    // epilogue mapping (threads 0..255): output = (s, o, hh)
    const int s   = tid & 31;
    const int o   = (tid >> 5) & 3;
    const int hh  = (tid >> 7) & 1;
    const int colE = col0 + ((s >> 3) << 2) + o;
    const int rowE = row0 + ((s & 7) << 2) + (hh << 1);
    const size_t eo0 = (size_t)rowE * H_DIM + colE;
    const size_t eo1 = eo0 + H_DIM;

    // prefetch xp for step 0
    float xp0 = 0.f, xp1 = 0.f;
    if (tid < 256) { xp0 = out[eo0]; xp1 = out[eo1]; }

    for (int t = 0; t < T_STEPS; ++t) {
        const float* gh  = g_ht[t & 1];
        float*       ghn = g_ht[(t + 1) & 1];
        float*       outt = out + (size_t)t * BATCH * H_DIM;

        ull acc[2][4];   // [row-pair][col]
#pragma unroll
        for (int j = 0; j < 4; ++j) { acc[0][j] = 0ULL; acc[1][j] = 0ULL; }

        const float* hp = gh + (size_t)kbase * BATCH + row0 + (rg << 2);
        const ull*   wp = wdup + (size_t)kbase * COLS_CTA + j0;

#pragma unroll 4
        for (int kk = 0; kk < KPW; kk += 2) {
            // h rows (4) for k and k+1, straight from L2 (bypass L1)
            uint4 ha = __ldcg((const uint4*)(hp + kk * BATCH));
            uint4 hb = __ldcg((const uint4*)(hp + (kk + 1) * BATCH));
            ull hA0 = mk64(ha.x, ha.y);   // rows r0,r0+1 @ k
            ull hA1 = mk64(ha.z, ha.w);   // rows r0+2,r0+3 @ k
            ull hB0 = mk64(hb.x, hb.y);   // @ k+1
            ull hB1 = mk64(hb.z, hb.w);

            const ull* wk = wp + kk * COLS_CTA;
            ulonglong2 w0 = *(const ulonglong2*)(wk);                 // k: cols j0,j0+1
            ulonglong2 w1 = *(const ulonglong2*)(wk + 2);             // k: cols j0+2,j0+3
            ulonglong2 w2 = *(const ulonglong2*)(wk + COLS_CTA);      // k+1
            ulonglong2 w3 = *(const ulonglong2*)(wk + COLS_CTA + 2);

            fma2(acc[0][0], hA0, w0.x); fma2(acc[1][0], hA1, w0.x);
            fma2(acc[0][1], hA0, w0.y); fma2(acc[1][1], hA1, w0.y);
            fma2(acc[0][2], hA0, w1.x); fma2(acc[1][2], hA1, w1.x);
            fma2(acc[0][3], hA0, w1.y); fma2(acc[1][3], hA1, w1.y);
            fma2(acc[0][0], hB0, w2.x); fma2(acc[1][0], hB1, w2.x);
            fma2(acc[0][1], hB0, w2.y); fma2(acc[1][1], hB1, w2.y);
            fma2(acc[0][2], hB0, w3.x); fma2(acc[1][2], hB1, w3.x);
            fma2(acc[0][3], hB0, w3.y); fma2(acc[1][3], hB1, w3.y);
        }

        // store partials: red[o][wid][lane], lane-contiguous
#pragma unroll
        for (int oo = 0; oo < 4; ++oo)
            red[(oo * NWARPS + wid) * 32 + lane] =
                make_ulonglong2(acc[0][oo], acc[1][oo]);
        __syncthreads();

        // distributed epilogue: 256 threads, one ull (2 outputs) each
        if (tid < 256) {
            ull a = 0ULL;
#pragma unroll
            for (int w = 0; w < NWARPS; ++w)
                a = add2(a, red_u[((o * NWARPS + w) * 32 + s) * 2 + hh]);

            float v0, v1;
            unpack2(a, v0, v1);
            v0 = tanhf(v0 + xp0);
            v1 = tanhf(v1 + xp1);

            // hidden state to output history
            outt[eo0] = v0;
            outt[eo1] = v1;

            // transposed copy for next step's loads (8B, aligned)
            *(float2*)&ghn[colE * BATCH + rowE] = make_float2(v0, v1);

            // prefetch next step's xp; latency hides under the grid barrier
            if (t + 1 < T_STEPS) {
                const float* outn = outt + BATCH * H_DIM;
                xp0 = outn[eo0];
                xp1 = outn[eo1];
            }
        }

        grid_barrier();
    }
}

// ---------------------------------------------------------------------------
extern "C" void kernel_launch(void* const* d_in, const int* in_sizes, int n_in,
                              void* d_out, int out_size)
{
    (void)in_sizes; (void)n_in; (void)out_size;
    const float* x = (const float*)d_in[0];
    const float* h = (const float*)d_in[1];
    const float* W = (const float*)d_in[2];
    const float* b = (const float*)d_in[3];
    float* out = (float*)d_out;

    // 1) xproj = x @ Wx + b  -> out
    dim3 grid_x(H_DIM / 64, (T_STEPS * BATCH) / 64);
    xproj_kernel<<<grid_x, 256>>>(x, W, b, out);

    // 2) persistent recurrent scan (weights 128KB + reduction 32KB smem)
    const size_t smem_bytes = (size_t)H_DIM * COLS_CTA * sizeof(ull)   // 131072
                            + 4 * NWARPS * 32 * sizeof(ulonglong2);    // + 32768
    static int smem_set = 0;
    if (!smem_set) {
        cudaFuncSetAttribute(scan_kernel, cudaFuncAttributeMaxDynamicSharedMemorySize,
                             (int)smem_bytes);
        smem_set = 1;
    }
    scan_kernel<<<NCTA, SCAN_THREADS, smem_bytes>>>(h, W, out);
}

// round 9
// speedup vs baseline: 1.8457x; 1.8457x over previous
#include <cuda_runtime.h>
#include <math.h>
#include <stdint.h>

typedef unsigned long long ull;

#define T_STEPS 1024
#define BATCH   64
#define IN_DIM  512
#define H_DIM   1024

#define NCTA         128
#define SCAN_THREADS 512
#define NWARPS       16
#define COLS_PER_CTA 8          // 128 CTAs * 8 cols = 1024
#define KPW          64         // k per warp (16 warps * 64 = 1024)
#define SUBK         16         // k per staged subslice
#define NSUB         (KPW / SUBK)       // 4 subslices, double-buffered
#define WPK_PITCH    1030       // ull pitch per column (bank-stagger)

// Transposed hidden state, double-buffered: g_ht[p][col*BATCH + row]
__device__ float g_ht[2][H_DIM * BATCH];
// Grid barrier: monotonic arrival counter + separately-polled epoch word
__device__ ull g_count = 0ULL;
__device__ ull g_epoch = 0ULL;

// ---------------------------------------------------------------------------
// packed f32x2 helpers (Blackwell sm_103a)
// ---------------------------------------------------------------------------
__device__ __forceinline__ ull pack2(float a, float b)
{
    ull r; asm("mov.b64 %0, {%1, %2};" : "=l"(r) : "f"(a), "f"(b)); return r;
}
__device__ __forceinline__ void unpack2(ull v, float& a, float& b)
{
    asm("mov.b64 {%0, %1}, %2;" : "=f"(a), "=f"(b) : "l"(v));
}
__device__ __forceinline__ void fma2(ull& acc, ull a, ull b)
{
    asm("fma.rn.f32x2 %0, %1, %2, %0;" : "+l"(acc) : "l"(a), "l"(b));
}
__device__ __forceinline__ ull add2(ull a, ull b)
{
    ull r; asm("add.rn.f32x2 %0, %1, %2;" : "=l"(r) : "l"(a), "l"(b)); return r;
}

// ---------------------------------------------------------------------------
// Kernel 1: xproj = x @ Wx + b  (out doubles as xproj buffer) — R6 version
// M=65536, K=512, N=1024. BM=64, BN=64, BK=16; 256 threads; 4x4 microtile.
// ---------------------------------------------------------------------------
__global__ void __launch_bounds__(256) xproj_kernel(
    const float* __restrict__ x,
    const float* __restrict__ W,     // full (IN+H, H); Wx = rows [0,512)
    const float* __restrict__ bias,
    float* __restrict__ out)
{
    __shared__ float As[16][64];     // [k][m]
    __shared__ float Bs[16][64];     // [k][n]

    const int tid  = threadIdx.x;
    const int row0 = blockIdx.y * 64;
    const int col0 = blockIdx.x * 64;

    const int ty = tid >> 4;               // 0..15
    const int tx = tid & 15;               // 0..15

    const int lmA = tid >> 2;              // 0..63
    const int lkA = (tid & 3) << 2;        // 0,4,8,12
    const int lkB = tid >> 4;              // 0..15
    const int lnB = (tid & 15) << 2;       // 0..60

    ull acc01[4], acc23[4];
#pragma unroll
    for (int i = 0; i < 4; ++i) { acc01[i] = 0ULL; acc23[i] = 0ULL; }

    const float* xg = x + (size_t)(row0 + lmA) * IN_DIM + lkA;

    for (int k0 = 0; k0 < IN_DIM; k0 += 16) {
        float4 av = *(const float4*)(xg + k0);
        As[lkA + 0][lmA] = av.x;
        As[lkA + 1][lmA] = av.y;
        As[lkA + 2][lmA] = av.z;
        As[lkA + 3][lmA] = av.w;

        float4 bv = *(const float4*)(W + (size_t)(k0 + lkB) * H_DIM + col0 + lnB);
        *(float4*)&Bs[lkB][lnB] = bv;

        __syncthreads();
#pragma unroll
        for (int k = 0; k < 16; ++k) {
            float4 a = *(const float4*)&As[k][ty << 2];
            ulonglong2 b = *(const ulonglong2*)&Bs[k][tx << 2];
            ull ax = pack2(a.x, a.x);
            ull ay = pack2(a.y, a.y);
            ull az = pack2(a.z, a.z);
            ull aw = pack2(a.w, a.w);
            fma2(acc01[0], ax, b.x); fma2(acc23[0], ax, b.y);
            fma2(acc01[1], ay, b.x); fma2(acc23[1], ay, b.y);
            fma2(acc01[2], az, b.x); fma2(acc23[2], az, b.y);
            fma2(acc01[3], aw, b.x); fma2(acc23[3], aw, b.y);
        }
        __syncthreads();
    }

    float4 bb = *(const float4*)(bias + col0 + (tx << 2));
#pragma unroll
    for (int i = 0; i < 4; ++i) {
        float s0, s1, s2, s3;
        unpack2(acc01[i], s0, s1);
        unpack2(acc23[i], s2, s3);
        float4 o;
        o.x = s0 + bb.x;
        o.y = s1 + bb.y;
        o.z = s2 + bb.z;
        o.w = s3 + bb.w;
        *(float4*)(out + (size_t)(row0 + (ty << 2) + i) * H_DIM + col0 + (tx << 2)) = o;
    }
}

// ---------------------------------------------------------------------------
// Scan kernel helpers
// ---------------------------------------------------------------------------
__device__ __forceinline__ void cp_async16(float* sdst, const float* gsrc)
{
    unsigned sa = (unsigned)__cvta_generic_to_shared(sdst);
    asm volatile("cp.async.cg.shared.global [%0], [%1], 16;\n" :: "r"(sa), "l"(gsrc));
}

// warp-private subslice staging: SUBK*BATCH = 1024 floats = 256 float4
// lane copies 8 float4s (idx = lane + i*32), fully coalesced
__device__ __forceinline__ void stage_sub(const float* gsrc, float* sdst, int lane)
{
#pragma unroll
    for (int i = 0; i < 8; ++i) {
        int idx = lane + i * 32;
        cp_async16(sdst + idx * 4, gsrc + idx * 4);
    }
}

// Counter+epoch barrier: RMWs on g_count never contend with the read-polls,
// which target only g_epoch.
__device__ __forceinline__ void grid_barrier()
{
    __syncthreads();
    if (threadIdx.x == 0) {
        __threadfence();
        ull old = atomicAdd(&g_count, 1ULL);
        ull target = (old / NCTA + 1ULL) * (ull)NCTA;
        if (old + 1ULL == target) {
            asm volatile("st.release.gpu.global.u64 [%0], %1;" :: "l"(&g_epoch), "l"(target));
        } else {
            ull cur;
            do {
                asm volatile("ld.acquire.gpu.global.u64 %0, [%1];" : "=l"(cur) : "l"(&g_epoch));
            } while (cur < target);
        }
    }
    __syncthreads();
}

// ---------------------------------------------------------------------------
// Kernel 2: persistent recurrent scan — per-warp pipelined staging.
// 128 CTAs x 512 threads (16 warps). CTA owns 8 output columns.
// Warp w owns k in [w*64, w*64+64), staged as 4 subslices of 16 k into
// warp-PRIVATE double buffers via its own cp.async commit/wait (+syncwarp).
// NO __syncthreads in the k-loop — warps pipeline independently.
// Microtile: 4 rows x 4 cols per thread (lane = rg(0..15) + 16*cg(0..1)).
// Weights pre-packed (w,w) in smem [c][k]. Reduction in dedicated smem.
// ---------------------------------------------------------------------------
__global__ void __launch_bounds__(SCAN_THREADS) scan_kernel(
    const float* __restrict__ hinit,  // initial h (B,H)
    const float* __restrict__ W,      // Wh = rows [512, 1536)
    float* __restrict__ out)
{
    extern __shared__ float smem[];
    ull*   wpk  = (ull*)smem;                            // 8 x 1030 ull = 65920 B
    float* hball = smem + 2 * 8 * WPK_PITCH;             // 16 warps x 2 x 1024 f = 128 KB
    ulonglong2* red = (ulonglong2*)(hball + NWARPS * 2 * SUBK * BATCH);  // 32 KB
    ull* red_u = (ull*)red;
    (void)red_u;

    const int tid  = threadIdx.x;
    const int wid  = tid >> 5;                // warp 0..15
    const int lane = tid & 31;
    const int rg   = lane & 15;               // rows rg*4..rg*4+3
    const int cg   = lane >> 4;               // cols cg*4..cg*4+3
    const int col0 = blockIdx.x * COLS_PER_CTA;
    const int c0   = cg * 4;
    const int r0   = rg * 4;

    float* myb = hball + wid * (2 * SUBK * BATCH);   // my double buffer (2 x 1024 f)

    // Prologue A: transpose my 8 columns of initial h into g_ht[0]
    {
        int cc = tid >> 6;        // 0..7
        int r  = tid & 63;        // 0..63
        g_ht[0][(col0 + cc) * BATCH + r] = hinit[(size_t)r * H_DIM + col0 + cc];
    }

    // Prologue B: pre-pack resident Wh slice: wpk[cc][k] = (w, w)
    for (int i = tid; i < H_DIM * COLS_PER_CTA; i += SCAN_THREADS) {
        int cc = i >> 10;
        int k  = i & 1023;
        float w = W[(size_t)(IN_DIM + k) * H_DIM + col0 + cc];
        wpk[cc * WPK_PITCH + k] = pack2(w, w);
    }

    grid_barrier();   // all transposes visible before step-0 staging

    // per-thread weight row pointers (4 cols), absolute-k indexed
    const ull* wp0 = wpk + (c0 + 0) * WPK_PITCH;
    const ull* wp1 = wpk + (c0 + 1) * WPK_PITCH;
    const ull* wp2 = wpk + (c0 + 2) * WPK_PITCH;
    const ull* wp3 = wpk + (c0 + 3) * WPK_PITCH;

    const int kb0 = wid * KPW;

    // epilogue thread's output column and row offsets (warps 0..3 only)
    const int  colE = col0 + c0 + wid;                  // valid when wid<4
    const size_t eo0 = (size_t)(r0 + 0) * H_DIM + colE;
    const size_t eo1 = (size_t)(r0 + 1) * H_DIM + colE;
    const size_t eo2 = (size_t)(r0 + 2) * H_DIM + colE;
    const size_t eo3 = (size_t)(r0 + 3) * H_DIM + colE;

    // prefetch xp for step 0 (epilogue warps)
    float xp0 = 0.f, xp1 = 0.f, xp2 = 0.f, xp3 = 0.f;
    if (wid < 4) {
        xp0 = out[eo0]; xp1 = out[eo1]; xp2 = out[eo2]; xp3 = out[eo3];
    }

    for (int t = 0; t < T_STEPS; ++t) {
        const float* gh  = g_ht[t & 1];
        float*       ghn = g_ht[(t + 1) & 1];
        float*       outt = out + (size_t)t * BATCH * H_DIM;

        ull acc[2][4];
#pragma unroll
        for (int j = 0; j < 4; ++j) { acc[0][j] = 0ULL; acc[1][j] = 0ULL; }

        // stage my subslice 0
        stage_sub(gh + (size_t)kb0 * BATCH, myb, lane);
        asm volatile("cp.async.commit_group;\n" ::: "memory");

#pragma unroll
        for (int s = 0; s < NSUB; ++s) {
            if (s + 1 < NSUB) {
                stage_sub(gh + (size_t)(kb0 + (s + 1) * SUBK) * BATCH,
                          myb + ((s + 1) & 1) * (SUBK * BATCH), lane);
                asm volatile("cp.async.commit_group;\n" ::: "memory");
                asm volatile("cp.async.wait_group 1;\n" ::: "memory");
            } else {
                asm volatile("cp.async.wait_group 0;\n" ::: "memory");
            }
            __syncwarp();

            const float* hb = myb + (s & 1) * (SUBK * BATCH) + r0;
            const int kw = kb0 + s * SUBK;
#pragma unroll
            for (int kk = 0; kk < SUBK; kk += 2) {
                const float* hp = hb + kk * BATCH;
                ulonglong2 hA = *(const ulonglong2*)(hp);          // rows r0..r0+3, k
                ulonglong2 hB = *(const ulonglong2*)(hp + BATCH);  // k+1
                ulonglong2 w0 = *(const ulonglong2*)(wp0 + kw + kk);
                ulonglong2 w1 = *(const ulonglong2*)(wp1 + kw + kk);
                ulonglong2 w2 = *(const ulonglong2*)(wp2 + kw + kk);
                ulonglong2 w3 = *(const ulonglong2*)(wp3 + kw + kk);
                fma2(acc[0][0], hA.x, w0.x); fma2(acc[1][0], hA.y, w0.x);
                fma2(acc[0][1], hA.x, w1.x); fma2(acc[1][1], hA.y, w1.x);
                fma2(acc[0][2], hA.x, w2.x); fma2(acc[1][2], hA.y, w2.x);
                fma2(acc[0][3], hA.x, w3.x); fma2(acc[1][3], hA.y, w3.x);
                fma2(acc[0][0], hB.x, w0.y); fma2(acc[1][0], hB.y, w0.y);
                fma2(acc[0][1], hB.x, w1.y); fma2(acc[1][1], hB.y, w1.y);
                fma2(acc[0][2], hB.x, w2.y); fma2(acc[1][2], hB.y, w2.y);
                fma2(acc[0][3], hB.x, w3.y); fma2(acc[1][3], hB.y, w3.y);
            }
            __syncwarp();   // all lanes done reading before buffer is re-staged
        }

        // store partials: red[j][s=wid][lane], lane-contiguous
#pragma unroll
        for (int j = 0; j < 4; ++j)
            red[(j * NWARPS + wid) * 32 + lane] = make_ulonglong2(acc[0][j], acc[1][j]);
        __syncthreads();

        // distributed epilogue: warp e reduces + writes column j=e
        if (wid < 4) {
            ull s01 = 0ULL, s23 = 0ULL;
#pragma unroll
            for (int s = 0; s < NWARPS; ++s) {
                ulonglong2 p = red[(wid * NWARPS + s) * 32 + lane];
                s01 = add2(s01, p.x);
                s23 = add2(s23, p.y);
            }
            float v0, v1, v2, v3;
            unpack2(s01, v0, v1);
            unpack2(s23, v2, v3);
            v0 = tanhf(v0 + xp0);
            v1 = tanhf(v1 + xp1);
            v2 = tanhf(v2 + xp2);
            v3 = tanhf(v3 + xp3);

            // hidden state to output history (column-scattered, small)
            outt[eo0] = v0;
            outt[eo1] = v1;
            outt[eo2] = v2;
            outt[eo3] = v3;

            // transposed copy for next step's staging (coalesced float4)
            *(float4*)&ghn[colE * BATCH + r0] = make_float4(v0, v1, v2, v3);

            // prefetch next step's xp; latency hides under the grid barrier
            if (t + 1 < T_STEPS) {
                const float* outn = outt + BATCH * H_DIM;
                xp0 = outn[eo0]; xp1 = outn[eo1]; xp2 = outn[eo2]; xp3 = outn[eo3];
            }
        }

        grid_barrier();
    }
}

// ---------------------------------------------------------------------------
extern "C" void kernel_launch(void* const* d_in, const int* in_sizes, int n_in,
                              void* d_out, int out_size)
{
    (void)in_sizes; (void)n_in; (void)out_size;
    const float* x = (const float*)d_in[0];
    const float* h = (const float*)d_in[1];
    const float* W = (const float*)d_in[2];
    const float* b = (const float*)d_in[3];
    float* out = (float*)d_out;

    // 1) xproj = x @ Wx + b  -> out
    dim3 grid_x(H_DIM / 64, (T_STEPS * BATCH) / 64);
    xproj_kernel<<<grid_x, 256>>>(x, W, b, out);

    // 2) persistent recurrent scan
    // smem: weights 65920 + warp buffers 131072 + reduction 32768 = 229760 B
    const size_t smem_bytes = (2 * 8 * WPK_PITCH + NWARPS * 2 * SUBK * BATCH) * sizeof(float)
                            + 4 * NWARPS * 32 * sizeof(ulonglong2);
    static int smem_set = 0;
    if (!smem_set) {
        cudaFuncSetAttribute(scan_kernel, cudaFuncAttributeMaxDynamicSharedMemorySize,
                             (int)smem_bytes);
        smem_set = 1;
    }
    scan_kernel<<<NCTA, SCAN_THREADS, smem_bytes>>>(h, W, out);
}